// round 4
// baseline (speedup 1.0000x reference)
#include <cuda_runtime.h>
#include <math.h>

#define NN 10000
#define EE 320000
#define FF 128
#define HH 128
#define TT 16
#define OO 128

// ---------------- static device scratch ----------------
__device__ float g_xT[TT * NN * FF];      // (T,N,F) transposed input
__device__ float g_hseq[NN * TT * HH];    // (N,T,H) top-layer states
__device__ float g_h0[NN * HH];
__device__ float g_h1[NN * HH];
__device__ float g_agg[NN * HH];          // A_norm @ input
__device__ float g_rh[NN * HH];           // r * hp
__device__ float g_zg[NN * HH];           // sigmoid(z)
__device__ float g_ctx[NN * HH];
__device__ int   g_rowptr[NN + 1];
__device__ int   g_count[NN];
__device__ float g_degsum[NN];
__device__ int   g_cursor[NN];
__device__ int   g_cols[EE];
__device__ float g_vals[EE];
__device__ float g_dinv[NN];
__device__ float g_selfn[NN];
__device__ float g_Wzr[2 * 256 * 256];    // per layer: rows 0..127 agg-weights, 128..255 hp-weights; cols [z|r]
__device__ float g_Wh[2 * 256 * 128];
__device__ float g_bzr[2 * 256];
__device__ float g_bh[2 * 128];

struct WPtrs {
    const float* Wc[3];
    const float* bc[3];
    const float* Wl[3];
    const float* bl[3];
};

// ---------------- preprocessing ----------------

// Fused weights: W_top = Wc @ Wl_top, W_bot = Wl_bot, bias = bc @ Wl_top + bl.
__global__ void k_prep(WPtrs P) {
    int lg = blockIdx.y;                // 0..5
    int l = lg / 3, g = lg % 3;
    int i = blockIdx.x;                 // row 0..127
    int j = threadIdx.x;                // col 0..127
    const float* Wc = P.Wc[g] + l * HH * HH;
    const float* Wl = P.Wl[g] + l * 2 * HH * HH;
    float c = 0.f;
    for (int k = 0; k < HH; k++) c += Wc[i * HH + k] * Wl[k * HH + j];
    float bot = Wl[(HH + i) * HH + j];
    if (g < 2) {
        g_Wzr[l * 256 * 256 + i * 256 + g * HH + j] = c;
        g_Wzr[l * 256 * 256 + (HH + i) * 256 + g * HH + j] = bot;
    } else {
        g_Wh[l * 256 * 128 + i * 128 + j] = c;
        g_Wh[l * 256 * 128 + (HH + i) * 128 + j] = bot;
    }
    if (i == 0) {
        const float* bc = P.bc[g] + l * HH;
        const float* bl = P.bl[g] + l * HH;
        float b = 0.f;
        for (int k = 0; k < HH; k++) b += bc[k] * Wl[k * HH + j];
        b += bl[j];
        if (g < 2) g_bzr[l * 256 + g * HH + j] = b;
        else       g_bh[l * 128 + j] = b;
    }
}

// Transpose x (N,F,T)->(T,N,F) and zero states/counters.
__global__ void k_init(const float* __restrict__ x) {
    int idx = blockIdx.x * blockDim.x + threadIdx.x;   // over N*F
    if (idx >= NN * FF) return;
    const float4* xr = (const float4*)(x + (size_t)idx * TT);
    float v[16];
    float4 q;
    q = xr[0]; v[0]=q.x; v[1]=q.y; v[2]=q.z; v[3]=q.w;
    q = xr[1]; v[4]=q.x; v[5]=q.y; v[6]=q.z; v[7]=q.w;
    q = xr[2]; v[8]=q.x; v[9]=q.y; v[10]=q.z; v[11]=q.w;
    q = xr[3]; v[12]=q.x; v[13]=q.y; v[14]=q.z; v[15]=q.w;
#pragma unroll
    for (int t = 0; t < TT; t++)
        g_xT[t * (NN * FF) + idx] = v[t];
    if (idx < NN * HH) { g_h0[idx] = 0.f; g_h1[idx] = 0.f; }
    if (idx < NN) { g_count[idx] = 0; g_degsum[idx] = 0.f; }
}

__global__ void k_count(const int* __restrict__ ei, const float* __restrict__ ew) {
    int e = blockIdx.x * blockDim.x + threadIdx.x;
    if (e >= EE) return;
    int d = ei[EE + e];
    atomicAdd(&g_count[d], 1);
    atomicAdd(&g_degsum[d], ew[e]);
}

__global__ void k_scan() {
    __shared__ int sdata[1024];
    __shared__ int s_off;
    int tid = threadIdx.x;
    // dinv from degree sums (independent of the scan itself)
    for (int i = tid; i < NN; i += 1024) {
        float dinv = rsqrtf(g_degsum[i] + 1.0f);
        g_dinv[i] = dinv;
        g_selfn[i] = dinv * dinv;
    }
    if (tid == 0) s_off = 0;
    __syncthreads();
    for (int base = 0; base < NN; base += 1024) {
        int v = (base + tid < NN) ? g_count[base + tid] : 0;
        sdata[tid] = v;
        __syncthreads();
        for (int d = 1; d < 1024; d <<= 1) {
            int t2 = (tid >= d) ? sdata[tid - d] : 0;
            __syncthreads();
            sdata[tid] += t2;
            __syncthreads();
        }
        int excl = sdata[tid] - v;
        if (base + tid < NN) {
            g_rowptr[base + tid] = s_off + excl;
            g_cursor[base + tid] = s_off + excl;
        }
        __syncthreads();
        int chunk_total = sdata[1023];
        if (tid == 0) s_off += chunk_total;
        __syncthreads();
    }
    if (tid == 0) g_rowptr[NN] = s_off;
}

__global__ void k_scatter(const int* __restrict__ ei, const float* __restrict__ ew) {
    int e = blockIdx.x * blockDim.x + threadIdx.x;
    if (e >= EE) return;
    int s = ei[e], d = ei[EE + e];
    int p = atomicAdd(&g_cursor[d], 1);
    g_cols[p] = s;
    g_vals[p] = ew[e] * g_dinv[s] * g_dinv[d];
}

// ---------------- main-loop kernels ----------------

// g_agg[row] = A_norm @ in (incl. self-loop term)
__global__ void k_spmm(const float* __restrict__ in) {
    int row = blockIdx.x * blockDim.y + threadIdx.y;
    if (row >= NN) return;
    int lane = threadIdx.x;
    const float4* in4 = (const float4*)in;
    float sn = g_selfn[row];
    float4 hv = in4[row * 32 + lane];
    float ax = sn * hv.x, ay = sn * hv.y, az = sn * hv.z, aw = sn * hv.w;
    float bx = 0.f, by = 0.f, bz = 0.f, bw = 0.f;
    int p = g_rowptr[row], pe = g_rowptr[row + 1];
    for (; p + 1 < pe; p += 2) {
        float v0 = g_vals[p],     v1 = g_vals[p + 1];
        int   c0 = g_cols[p],     c1 = g_cols[p + 1];
        float4 b0 = in4[c0 * 32 + lane];
        float4 b1 = in4[c1 * 32 + lane];
        ax += v0 * b0.x; ay += v0 * b0.y; az += v0 * b0.z; aw += v0 * b0.w;
        bx += v1 * b1.x; by += v1 * b1.y; bz += v1 * b1.z; bw += v1 * b1.w;
    }
    if (p < pe) {
        float v0 = g_vals[p]; int c0 = g_cols[p];
        float4 b0 = in4[c0 * 32 + lane];
        ax += v0 * b0.x; ay += v0 * b0.y; az += v0 * b0.z; aw += v0 * b0.w;
    }
    ((float4*)g_agg)[row * 32 + lane] =
        make_float4(ax + bx, ay + by, az + bz, aw + bw);
}

// Fused GEMM. Logical A is [A1 | A2] (M x 256), each half M x 128 row-major.
// B is K x ldb row-major. BM x 128 tile, BK=8, 256 threads, (BM/16) x 8 microtile.
// MODE 0: z/r gate.  blockIdx.y==0 -> g_zg = sigmoid(acc+b);  ==1 -> g_rh = sigmoid(acc+b)*hp
// MODE 1: candidate. h_new = z*hp + (1-z)*tanh(acc+b); update hstate, optional hseq
// MODE 2: plain Cout = acc + b
template<int BM, int MODE>
__global__ void __launch_bounds__(256, 2)
k_gemm_f(const float* __restrict__ A1, const float* __restrict__ A2,
         const float* __restrict__ B, const float* __restrict__ bias,
         float* __restrict__ hstate, float* __restrict__ Cout,
         int M, int K, int ldb, int t, int wseq) {
    constexpr int MI = BM / 16;
    __shared__ float As[8][132];
    __shared__ float Bs[8][132];
    const int tid = threadIdx.x;
    const int tx = tid & 15, ty = tid >> 4;
    const int row0 = blockIdx.x * BM;
    const int col0 = blockIdx.y * 128;

    float acc[MI][8];
#pragma unroll
    for (int i = 0; i < MI; i++)
#pragma unroll
        for (int j = 0; j < 8; j++) acc[i][j] = 0.f;

    const int am = tid >> 1, akq = (tid & 1) * 4;   // A-load role (tid < BM*2)
    const int bkb = tid >> 5, bn4 = (tid & 31) * 4; // B-load role (all threads)

    auto loadA = [&](int kt) -> float4 {
        if (BM == 64 && tid >= 128) return make_float4(0.f, 0.f, 0.f, 0.f);
        int grow = row0 + am;
        if (grow >= M) return make_float4(0.f, 0.f, 0.f, 0.f);
        int kk = kt + akq;
        const float* p = (kk < 128) ? (A1 + (size_t)grow * 128 + kk)
                                    : (A2 + (size_t)grow * 128 + (kk - 128));
        return *(const float4*)p;
    };
    auto loadB = [&](int kt) -> float4 {
        return *(const float4*)&B[(size_t)(kt + bkb) * ldb + col0 + bn4];
    };

    float4 apre = loadA(0);
    float4 bpre = loadB(0);

    for (int kt = 0; kt < K; kt += 8) {
        if (tid < BM * 2) {
            As[akq + 0][am] = apre.x;
            As[akq + 1][am] = apre.y;
            As[akq + 2][am] = apre.z;
            As[akq + 3][am] = apre.w;
        }
        *(float4*)&Bs[bkb][bn4] = bpre;
        __syncthreads();
        if (kt + 8 < K) { apre = loadA(kt + 8); bpre = loadB(kt + 8); }
#pragma unroll
        for (int k = 0; k < 8; k++) {
            float av[MI], bv[8];
            *(float4*)&av[0] = *(const float4*)&As[k][ty * MI];
            if (MI == 8) *(float4*)&av[4] = *(const float4*)&As[k][ty * MI + 4];
            *(float4*)&bv[0] = *(const float4*)&Bs[k][tx * 8];
            *(float4*)&bv[4] = *(const float4*)&Bs[k][tx * 8 + 4];
#pragma unroll
            for (int i = 0; i < MI; i++)
#pragma unroll
                for (int j = 0; j < 8; j++) acc[i][j] += av[i] * bv[j];
        }
        __syncthreads();
    }

    float bb[8];
#pragma unroll
    for (int j = 0; j < 8; j++) bb[j] = bias[col0 + tx * 8 + j];

#pragma unroll
    for (int i = 0; i < MI; i++) {
        int grow = row0 + ty * MI + i;
        if (grow >= M) continue;
        size_t base = (size_t)grow * 128 + tx * 8;
        float vv[8];
#pragma unroll
        for (int j = 0; j < 8; j++) vv[j] = acc[i][j] + bb[j];
        if (MODE == 0) {
#pragma unroll
            for (int j = 0; j < 8; j++) vv[j] = 1.f / (1.f + expf(-vv[j]));
            if (blockIdx.y == 0) {
                *(float4*)&g_zg[base]     = *(float4*)&vv[0];
                *(float4*)&g_zg[base + 4] = *(float4*)&vv[4];
            } else {
                float hv[8];
                *(float4*)&hv[0] = *(const float4*)&hstate[base];
                *(float4*)&hv[4] = *(const float4*)&hstate[base + 4];
#pragma unroll
                for (int j = 0; j < 8; j++) vv[j] *= hv[j];
                *(float4*)&g_rh[base]     = *(float4*)&vv[0];
                *(float4*)&g_rh[base + 4] = *(float4*)&vv[4];
            }
        } else if (MODE == 1) {
            float zv[8], hv[8];
            *(float4*)&zv[0] = *(const float4*)&g_zg[base];
            *(float4*)&zv[4] = *(const float4*)&g_zg[base + 4];
            *(float4*)&hv[0] = *(const float4*)&hstate[base];
            *(float4*)&hv[4] = *(const float4*)&hstate[base + 4];
#pragma unroll
            for (int j = 0; j < 8; j++) {
                float ht = tanhf(vv[j]);
                vv[j] = zv[j] * hv[j] + (1.f - zv[j]) * ht;
            }
            *(float4*)&hstate[base]     = *(float4*)&vv[0];
            *(float4*)&hstate[base + 4] = *(float4*)&vv[4];
            if (wseq) {
                size_t sb = (size_t)grow * (TT * HH) + t * HH + tx * 8;
                *(float4*)&g_hseq[sb]     = *(float4*)&vv[0];
                *(float4*)&g_hseq[sb + 4] = *(float4*)&vv[4];
            }
        } else {
            *(float4*)&Cout[base]     = *(float4*)&vv[0];
            *(float4*)&Cout[base + 4] = *(float4*)&vv[4];
        }
    }
}

// Temporal attention: warp per node (att_b cancels inside softmax).
__global__ void __launch_bounds__(128)
k_attn(const float* __restrict__ attW) {
    int n = blockIdx.x * blockDim.y + threadIdx.y;
    if (n >= NN) return;
    int lane = threadIdx.x;
    float4 aw = ((const float4*)attW)[lane];
    const float4* h4 = (const float4*)g_hseq + n * (TT * HH / 4) + lane;
    float4 hv[16];
    float s[16];
#pragma unroll
    for (int t = 0; t < TT; t++) {
        hv[t] = h4[t * 32];
        float d = hv[t].x * aw.x + hv[t].y * aw.y + hv[t].z * aw.z + hv[t].w * aw.w;
#pragma unroll
        for (int o = 16; o > 0; o >>= 1) d += __shfl_xor_sync(0xffffffffu, d, o);
        s[t] = d;
    }
    float m = s[0];
#pragma unroll
    for (int t = 1; t < TT; t++) m = fmaxf(m, s[t]);
    float sum = 0.f;
#pragma unroll
    for (int t = 0; t < TT; t++) { s[t] = expf(s[t] - m); sum += s[t]; }
    float inv = 1.f / sum;
    float4 c = make_float4(0.f, 0.f, 0.f, 0.f);
#pragma unroll
    for (int t = 0; t < TT; t++) {
        float w = s[t] * inv;
        c.x += w * hv[t].x; c.y += w * hv[t].y; c.z += w * hv[t].z; c.w += w * hv[t].w;
    }
    ((float4*)g_ctx)[n * 32 + lane] = c;
}

// ---------------- launch ----------------

extern "C" void kernel_launch(void* const* d_in, const int* in_sizes, int n_in,
                              void* d_out, int out_size) {
    const float* x   = (const float*)d_in[0];
    const int*   ei  = (const int*)d_in[1];
    const float* ew  = (const float*)d_in[2];
    WPtrs P;
    P.Wc[0] = (const float*)d_in[3];  P.bc[0] = (const float*)d_in[4];
    P.Wl[0] = (const float*)d_in[5];  P.bl[0] = (const float*)d_in[6];
    P.Wc[1] = (const float*)d_in[7];  P.bc[1] = (const float*)d_in[8];
    P.Wl[1] = (const float*)d_in[9];  P.bl[1] = (const float*)d_in[10];
    P.Wc[2] = (const float*)d_in[11]; P.bc[2] = (const float*)d_in[12];
    P.Wl[2] = (const float*)d_in[13]; P.bl[2] = (const float*)d_in[14];
    const float* attW = (const float*)d_in[15];
    const float* outW = (const float*)d_in[17];
    const float* outb = (const float*)d_in[18];
    float* out = (float*)d_out;

    float *p_xT, *p_h0, *p_h1, *p_agg, *p_rh, *p_ctx, *p_Wzr, *p_Wh, *p_bzr, *p_bh;
    cudaGetSymbolAddress((void**)&p_xT,  g_xT);
    cudaGetSymbolAddress((void**)&p_h0,  g_h0);
    cudaGetSymbolAddress((void**)&p_h1,  g_h1);
    cudaGetSymbolAddress((void**)&p_agg, g_agg);
    cudaGetSymbolAddress((void**)&p_rh,  g_rh);
    cudaGetSymbolAddress((void**)&p_ctx, g_ctx);
    cudaGetSymbolAddress((void**)&p_Wzr, g_Wzr);
    cudaGetSymbolAddress((void**)&p_Wh,  g_Wh);
    cudaGetSymbolAddress((void**)&p_bzr, g_bzr);
    cudaGetSymbolAddress((void**)&p_bh,  g_bh);

    const int GX128 = (NN + 127) / 128;             // 79
    const int GX64  = (NN + 63) / 64;               // 157

    k_prep<<<dim3(HH, 6), HH>>>(P);
    k_init<<<(NN * FF + 255) / 256, 256>>>(x);
    k_count<<<(EE + 255) / 256, 256>>>(ei, ew);
    k_scan<<<1, 1024>>>();
    k_scatter<<<(EE + 255) / 256, 256>>>(ei, ew);

    for (int t = 0; t < TT; t++) {
        // ---- layer 0 (input = x_t) ----
        k_spmm<<<(NN + 7) / 8, dim3(32, 8)>>>(p_xT + (size_t)t * NN * FF);
        k_gemm_f<128, 0><<<dim3(GX128, 2), 256>>>(p_agg, p_h0, p_Wzr, p_bzr,
                                                  p_h0, nullptr, NN, 256, 256, 0, 0);
        k_gemm_f<64, 1><<<dim3(GX64, 1), 256>>>(p_agg, p_rh, p_Wh, p_bh,
                                                p_h0, nullptr, NN, 256, 128, t, 0);
        // ---- layer 1 (input = new h0) ----
        k_spmm<<<(NN + 7) / 8, dim3(32, 8)>>>(p_h0);
        k_gemm_f<128, 0><<<dim3(GX128, 2), 256>>>(p_agg, p_h1, p_Wzr + 256 * 256, p_bzr + 256,
                                                  p_h1, nullptr, NN, 256, 256, 0, 0);
        k_gemm_f<64, 1><<<dim3(GX64, 1), 256>>>(p_agg, p_rh, p_Wh + 256 * 128, p_bh + 128,
                                                p_h1, nullptr, NN, 256, 128, t, 1);
    }

    k_attn<<<(NN + 3) / 4, dim3(32, 4)>>>(attW);
    k_gemm_f<64, 2><<<dim3(GX64, 1), 256>>>(p_ctx, nullptr, outW, outb,
                                            nullptr, out, NN, 128, 128, 0, 0);
}

// round 6
// speedup vs baseline: 1.1768x; 1.1768x over previous
#include <cuda_runtime.h>
#include <math.h>

#define NN 10000
#define EE 320000
#define FF 128
#define HH 128
#define TT 16
#define OO 128

// ---------------- static device scratch ----------------
__device__ float g_xT[TT * NN * FF];      // (T,N,F) transposed input
__device__ float g_hseq[NN * TT * HH];    // (N,T,H) top-layer states
__device__ float g_h0[NN * HH];
__device__ float g_h1[NN * HH];
__device__ float g_agg[NN * HH];          // A_norm @ input
__device__ float g_rh[NN * HH];           // r * hp
__device__ float g_zg[NN * HH];           // sigmoid(z)
__device__ float g_ctx[NN * HH];
__device__ int   g_rowptr[NN + 1];
__device__ int   g_count[NN];
__device__ float g_degsum[NN];
__device__ int   g_cursor[NN];
__device__ int   g_cols[EE];
__device__ float g_vals[EE];
__device__ float g_dinv[NN];
__device__ float g_selfn[NN];
__device__ float g_Wzr[2 * 256 * 256];    // per layer: rows 0..127 agg-W, 128..255 hp-W; cols [z|r]
__device__ float g_Wh[2 * 256 * 128];
__device__ float g_bzr[2 * 256];
__device__ float g_bh[2 * 128];

struct WPtrs {
    const float* Wc[3];
    const float* bc[3];
    const float* Wl[3];
    const float* bl[3];
};

// ---------------- preprocessing ----------------

// Fused weights: W_top = Wc @ Wl_top, W_bot = Wl_bot, bias = bc @ Wl_top + bl.
// Also zeroes the edge counters (needed fresh every graph replay).
__global__ void k_prep(WPtrs P) {
    int flat = (blockIdx.y * gridDim.x + blockIdx.x) * blockDim.x + threadIdx.x;
    if (flat < NN) { g_count[flat] = 0; g_degsum[flat] = 0.f; }

    int lg = blockIdx.y;                // 0..5
    int l = lg / 3, g = lg % 3;
    int i = blockIdx.x;                 // row 0..127
    int j = threadIdx.x;                // col 0..127
    const float* Wc = P.Wc[g] + l * HH * HH;
    const float* Wl = P.Wl[g] + l * 2 * HH * HH;
    float c = 0.f;
    for (int k = 0; k < HH; k++) c += Wc[i * HH + k] * Wl[k * HH + j];
    float bot = Wl[(HH + i) * HH + j];
    if (g < 2) {
        g_Wzr[l * 256 * 256 + i * 256 + g * HH + j] = c;
        g_Wzr[l * 256 * 256 + (HH + i) * 256 + g * HH + j] = bot;
    } else {
        g_Wh[l * 256 * 128 + i * 128 + j] = c;
        g_Wh[l * 256 * 128 + (HH + i) * 128 + j] = bot;
    }
    if (i == 0) {
        const float* bc = P.bc[g] + l * HH;
        const float* bl = P.bl[g] + l * HH;
        float b = 0.f;
        for (int k = 0; k < HH; k++) b += bc[k] * Wl[k * HH + j];
        b += bl[j];
        if (g < 2) g_bzr[l * 256 + g * HH + j] = b;
        else       g_bh[l * 128 + j] = b;
    }
}

// Transpose x (N,F,T)->(T,N,F), zero states, and count edges per dst.
__global__ void k_init(const float* __restrict__ x,
                       const int* __restrict__ ei, const float* __restrict__ ew) {
    int idx = blockIdx.x * blockDim.x + threadIdx.x;   // over N*F
    if (idx >= NN * FF) return;
    const float4* xr = (const float4*)(x + (size_t)idx * TT);
    float v[16];
    float4 q;
    q = xr[0]; v[0]=q.x; v[1]=q.y; v[2]=q.z; v[3]=q.w;
    q = xr[1]; v[4]=q.x; v[5]=q.y; v[6]=q.z; v[7]=q.w;
    q = xr[2]; v[8]=q.x; v[9]=q.y; v[10]=q.z; v[11]=q.w;
    q = xr[3]; v[12]=q.x; v[13]=q.y; v[14]=q.z; v[15]=q.w;
#pragma unroll
    for (int t = 0; t < TT; t++)
        g_xT[t * (NN * FF) + idx] = v[t];
    g_h0[idx] = 0.f;
    g_h1[idx] = 0.f;
    if (idx < EE) {
        int d = ei[EE + idx];
        atomicAdd(&g_count[d], 1);
        atomicAdd(&g_degsum[d], ew[idx]);
    }
}

__global__ void k_scan() {
    __shared__ int sdata[1024];
    __shared__ int s_off;
    int tid = threadIdx.x;
    for (int i = tid; i < NN; i += 1024) {
        float dinv = rsqrtf(g_degsum[i] + 1.0f);
        g_dinv[i] = dinv;
        g_selfn[i] = dinv * dinv;
    }
    if (tid == 0) s_off = 0;
    __syncthreads();
    for (int base = 0; base < NN; base += 1024) {
        int v = (base + tid < NN) ? g_count[base + tid] : 0;
        sdata[tid] = v;
        __syncthreads();
        for (int d = 1; d < 1024; d <<= 1) {
            int t2 = (tid >= d) ? sdata[tid - d] : 0;
            __syncthreads();
            sdata[tid] += t2;
            __syncthreads();
        }
        int excl = sdata[tid] - v;
        if (base + tid < NN) {
            g_rowptr[base + tid] = s_off + excl;
            g_cursor[base + tid] = s_off + excl;
        }
        __syncthreads();
        int chunk_total = sdata[1023];
        if (tid == 0) s_off += chunk_total;
        __syncthreads();
    }
    if (tid == 0) g_rowptr[NN] = s_off;
}

__global__ void k_scatter(const int* __restrict__ ei, const float* __restrict__ ew) {
    int e = blockIdx.x * blockDim.x + threadIdx.x;
    if (e >= EE) return;
    int s = ei[e], d = ei[EE + e];
    int p = atomicAdd(&g_cursor[d], 1);
    g_cols[p] = s;
    g_vals[p] = ew[e] * g_dinv[s] * g_dinv[d];
}

// ---------------- main-loop kernels ----------------

// g_agg[row] = A_norm @ in (incl. self-loop term)
__global__ void k_spmm(const float* __restrict__ in) {
    int row = blockIdx.x * blockDim.y + threadIdx.y;
    if (row >= NN) return;
    int lane = threadIdx.x;
    const float4* in4 = (const float4*)in;
    float sn = g_selfn[row];
    float4 hv = in4[row * 32 + lane];
    float ax = sn * hv.x, ay = sn * hv.y, az = sn * hv.z, aw = sn * hv.w;
    float bx = 0.f, by = 0.f, bz = 0.f, bw = 0.f;
    int p = g_rowptr[row], pe = g_rowptr[row + 1];
    for (; p + 1 < pe; p += 2) {
        float v0 = g_vals[p],     v1 = g_vals[p + 1];
        int   c0 = g_cols[p],     c1 = g_cols[p + 1];
        float4 b0 = in4[c0 * 32 + lane];
        float4 b1 = in4[c1 * 32 + lane];
        ax += v0 * b0.x; ay += v0 * b0.y; az += v0 * b0.z; aw += v0 * b0.w;
        bx += v1 * b1.x; by += v1 * b1.y; bz += v1 * b1.z; bw += v1 * b1.w;
    }
    if (p < pe) {
        float v0 = g_vals[p]; int c0 = g_cols[p];
        float4 b0 = in4[c0 * 32 + lane];
        ax += v0 * b0.x; ay += v0 * b0.y; az += v0 * b0.z; aw += v0 * b0.w;
    }
    ((float4*)g_agg)[row * 32 + lane] =
        make_float4(ax + bx, ay + by, az + bz, aw + bw);
}

// Fused GEMM, Round-1 proven shape: BM=128, BN=64, BK=16, 256 threads, 8x4 microtile.
// Logical A = [A1 | A2] (M x 2*128) read through two pointers; select is uniform per k-tile.
// MODE 0: gate GEMM (K=256, ldb=256). cols<128 -> g_zg = sigmoid; cols>=128 -> g_rh = sigmoid*hp.
// MODE 1: candidate (K=256, ldb=128). h_new = z*hp + (1-z)*tanh; writes hstate (+ hseq if wseq).
// MODE 2: plain (K=128, ldb=128). Cout = acc + bias.
template<int MODE>
__global__ void __launch_bounds__(256)
k_gemm(const float* __restrict__ A1, const float* __restrict__ A2,
       const float* __restrict__ B, const float* __restrict__ bias,
       float* __restrict__ hstate, float* __restrict__ Cout,
       int M, int K, int ldb, int t, int wseq) {
    __shared__ float As[16][128];
    __shared__ float Bs[16][64];
    const int tid = threadIdx.x;
    const int tx = tid & 15, ty = tid >> 4;
    const int row0 = blockIdx.x * 128;
    const int col0 = blockIdx.y * 64;

    float acc[8][4];
#pragma unroll
    for (int i = 0; i < 8; i++)
#pragma unroll
        for (int j = 0; j < 4; j++) acc[i][j] = 0.f;

    for (int kt = 0; kt < K; kt += 16) {
        const float* Asrc = (kt < 128) ? A1 + kt : A2 + (kt - 128);
#pragma unroll
        for (int i = 0; i < 2; i++) {
            int lid = tid + i * 256;
            int m = lid >> 2, kq = lid & 3;
            int grow = row0 + m;
            float4 a = (grow < M) ? *(const float4*)(Asrc + (size_t)grow * 128 + kq * 4)
                                  : make_float4(0.f, 0.f, 0.f, 0.f);
            As[kq * 4 + 0][m] = a.x;
            As[kq * 4 + 1][m] = a.y;
            As[kq * 4 + 2][m] = a.z;
            As[kq * 4 + 3][m] = a.w;
        }
        {
            int kb = tid >> 4, nq = tid & 15;
            float4 b = *(const float4*)&B[(size_t)(kt + kb) * ldb + col0 + nq * 4];
            *(float4*)&Bs[kb][nq * 4] = b;
        }
        __syncthreads();
#pragma unroll
        for (int k = 0; k < 16; k++) {
            float a[8], bf[4];
            *(float4*)&a[0] = *(const float4*)&As[k][ty * 8];
            *(float4*)&a[4] = *(const float4*)&As[k][ty * 8 + 4];
            *(float4*)&bf[0] = *(const float4*)&Bs[k][tx * 4];
#pragma unroll
            for (int i = 0; i < 8; i++)
#pragma unroll
                for (int j = 0; j < 4; j++) acc[i][j] += a[i] * bf[j];
        }
        __syncthreads();
    }

    float bb[4];
#pragma unroll
    for (int j = 0; j < 4; j++) bb[j] = bias[col0 + tx * 4 + j];

#pragma unroll
    for (int i = 0; i < 8; i++) {
        int grow = row0 + ty * 8 + i;
        if (grow >= M) continue;
        float vv[4];
#pragma unroll
        for (int j = 0; j < 4; j++) vv[j] = acc[i][j] + bb[j];

        if (MODE == 0) {
#pragma unroll
            for (int j = 0; j < 4; j++) vv[j] = 1.f / (1.f + expf(-vv[j]));
            if (col0 < 128) {
                size_t base = (size_t)grow * 128 + col0 + tx * 4;
                *(float4*)&g_zg[base] = *(float4*)&vv[0];
            } else {
                size_t base = (size_t)grow * 128 + (col0 - 128) + tx * 4;
                float4 hv = *(const float4*)&hstate[base];
                vv[0] *= hv.x; vv[1] *= hv.y; vv[2] *= hv.z; vv[3] *= hv.w;
                *(float4*)&g_rh[base] = *(float4*)&vv[0];
            }
        } else if (MODE == 1) {
            size_t base = (size_t)grow * 128 + col0 + tx * 4;
            float4 zv = *(const float4*)&g_zg[base];
            float4 hv = *(const float4*)&hstate[base];
            vv[0] = zv.x * hv.x + (1.f - zv.x) * tanhf(vv[0]);
            vv[1] = zv.y * hv.y + (1.f - zv.y) * tanhf(vv[1]);
            vv[2] = zv.z * hv.z + (1.f - zv.z) * tanhf(vv[2]);
            vv[3] = zv.w * hv.w + (1.f - zv.w) * tanhf(vv[3]);
            *(float4*)&hstate[base] = *(float4*)&vv[0];
            if (wseq) {
                size_t sb = (size_t)grow * (TT * HH) + t * HH + col0 + tx * 4;
                *(float4*)&g_hseq[sb] = *(float4*)&vv[0];
            }
        } else {
            size_t base = (size_t)grow * 128 + col0 + tx * 4;
            *(float4*)&Cout[base] = *(float4*)&vv[0];
        }
    }
}

// Temporal attention: warp per node (att_b cancels inside softmax).
__global__ void __launch_bounds__(128)
k_attn(const float* __restrict__ attW) {
    int n = blockIdx.x * blockDim.y + threadIdx.y;
    if (n >= NN) return;
    int lane = threadIdx.x;
    float4 aw = ((const float4*)attW)[lane];
    const float4* h4 = (const float4*)g_hseq + n * (TT * HH / 4) + lane;
    float4 hv[16];
    float s[16];
#pragma unroll
    for (int t = 0; t < TT; t++) {
        hv[t] = h4[t * 32];
        float d = hv[t].x * aw.x + hv[t].y * aw.y + hv[t].z * aw.z + hv[t].w * aw.w;
#pragma unroll
        for (int o = 16; o > 0; o >>= 1) d += __shfl_xor_sync(0xffffffffu, d, o);
        s[t] = d;
    }
    float m = s[0];
#pragma unroll
    for (int t = 1; t < TT; t++) m = fmaxf(m, s[t]);
    float sum = 0.f;
#pragma unroll
    for (int t = 0; t < TT; t++) { s[t] = expf(s[t] - m); sum += s[t]; }
    float inv = 1.f / sum;
    float4 c = make_float4(0.f, 0.f, 0.f, 0.f);
#pragma unroll
    for (int t = 0; t < TT; t++) {
        float w = s[t] * inv;
        c.x += w * hv[t].x; c.y += w * hv[t].y; c.z += w * hv[t].z; c.w += w * hv[t].w;
    }
    ((float4*)g_ctx)[n * 32 + lane] = c;
}

// ---------------- launch ----------------

extern "C" void kernel_launch(void* const* d_in, const int* in_sizes, int n_in,
                              void* d_out, int out_size) {
    const float* x   = (const float*)d_in[0];
    const int*   ei  = (const int*)d_in[1];
    const float* ew  = (const float*)d_in[2];
    WPtrs P;
    P.Wc[0] = (const float*)d_in[3];  P.bc[0] = (const float*)d_in[4];
    P.Wl[0] = (const float*)d_in[5];  P.bl[0] = (const float*)d_in[6];
    P.Wc[1] = (const float*)d_in[7];  P.bc[1] = (const float*)d_in[8];
    P.Wl[1] = (const float*)d_in[9];  P.bl[1] = (const float*)d_in[10];
    P.Wc[2] = (const float*)d_in[11]; P.bc[2] = (const float*)d_in[12];
    P.Wl[2] = (const float*)d_in[13]; P.bl[2] = (const float*)d_in[14];
    const float* attW = (const float*)d_in[15];
    const float* outW = (const float*)d_in[17];
    const float* outb = (const float*)d_in[18];
    float* out = (float*)d_out;

    float *p_xT, *p_h0, *p_h1, *p_agg, *p_rh, *p_ctx, *p_Wzr, *p_Wh, *p_bzr, *p_bh;
    cudaGetSymbolAddress((void**)&p_xT,  g_xT);
    cudaGetSymbolAddress((void**)&p_h0,  g_h0);
    cudaGetSymbolAddress((void**)&p_h1,  g_h1);
    cudaGetSymbolAddress((void**)&p_agg, g_agg);
    cudaGetSymbolAddress((void**)&p_rh,  g_rh);
    cudaGetSymbolAddress((void**)&p_ctx, g_ctx);
    cudaGetSymbolAddress((void**)&p_Wzr, g_Wzr);
    cudaGetSymbolAddress((void**)&p_Wh,  g_Wh);
    cudaGetSymbolAddress((void**)&p_bzr, g_bzr);
    cudaGetSymbolAddress((void**)&p_bh,  g_bh);

    const int GX = (NN + 127) / 128;                // 79

    k_prep<<<dim3(HH, 6), HH>>>(P);
    k_init<<<(NN * FF + 255) / 256, 256>>>(x, ei, ew);
    k_scan<<<1, 1024>>>();
    k_scatter<<<(EE + 255) / 256, 256>>>(ei, ew);

    for (int t = 0; t < TT; t++) {
        // ---- layer 0 (input = x_t) ----
        k_spmm<<<(NN + 7) / 8, dim3(32, 8)>>>(p_xT + (size_t)t * NN * FF);
        k_gemm<0><<<dim3(GX, 4), 256>>>(p_agg, p_h0, p_Wzr, p_bzr,
                                        p_h0, nullptr, NN, 256, 256, 0, 0);
        k_gemm<1><<<dim3(GX, 2), 256>>>(p_agg, p_rh, p_Wh, p_bh,
                                        p_h0, nullptr, NN, 256, 128, t, 0);
        // ---- layer 1 (input = new h0) ----
        k_spmm<<<(NN + 7) / 8, dim3(32, 8)>>>(p_h0);
        k_gemm<0><<<dim3(GX, 4), 256>>>(p_agg, p_h1, p_Wzr + 256 * 256, p_bzr + 256,
                                        p_h1, nullptr, NN, 256, 256, 0, 0);
        k_gemm<1><<<dim3(GX, 2), 256>>>(p_agg, p_rh, p_Wh + 256 * 128, p_bh + 128,
                                        p_h1, nullptr, NN, 256, 128, t, 1);
    }

    k_attn<<<(NN + 3) / 4, dim3(32, 4)>>>(attW);
    k_gemm<2><<<dim3(GX, 2), 256>>>(p_ctx, p_ctx, outW, outb,
                                    nullptr, out, NN, 128, 128, 0, 0);
}

// round 7
// speedup vs baseline: 1.2352x; 1.0497x over previous
#include <cuda_runtime.h>
#include <math.h>
#include <stdint.h>

#define NN 10000
#define EE 320000
#define FF 128
#define HH 128
#define TT 16
#define OO 128

// ---------------- static device scratch ----------------
__device__ float g_xT[TT * NN * FF];      // (T,N,F) transposed input
__device__ float g_hseq[NN * TT * HH];    // (N,T,H) top-layer states
__device__ float g_h0[NN * HH];
__device__ float g_h1[NN * HH];
__device__ float g_agg[NN * HH];          // A_norm @ input
__device__ float g_rh[NN * HH];           // r * hp
__device__ float g_zg[NN * HH];           // sigmoid(z)
__device__ float g_ctx[NN * HH];
__device__ int   g_rowptr[NN + 1];
__device__ int   g_count[NN];
__device__ float g_degsum[NN];
__device__ int   g_cursor[NN];
__device__ int   g_cols[EE];
__device__ float g_vals[EE];
__device__ float g_dinv[NN];
__device__ float g_selfn[NN];
__device__ float g_Wzr[2 * 256 * 256];    // per layer: rows 0..127 agg-W, 128..255 hp-W; cols [z|r]
__device__ float g_Wh[2 * 256 * 128];
__device__ float g_bzr[2 * 256];
__device__ float g_bh[2 * 128];

struct WPtrs {
    const float* Wc[3];
    const float* bc[3];
    const float* Wl[3];
    const float* bl[3];
};

// ---------------- tf32 helpers ----------------
__device__ __forceinline__ uint32_t f2tf(float x) {
    uint32_t r;
    asm("cvt.rna.tf32.f32 %0, %1;" : "=r"(r) : "f"(x));
    return r;
}

__device__ __forceinline__ void mma_tf32(float* c, const uint32_t* a, const uint32_t* b) {
    asm volatile(
        "mma.sync.aligned.m16n8k8.row.col.f32.tf32.tf32.f32 "
        "{%0,%1,%2,%3}, {%4,%5,%6,%7}, {%8,%9}, {%0,%1,%2,%3};\n"
        : "+f"(c[0]), "+f"(c[1]), "+f"(c[2]), "+f"(c[3])
        : "r"(a[0]), "r"(a[1]), "r"(a[2]), "r"(a[3]), "r"(b[0]), "r"(b[1]));
}

// ---------------- preprocessing ----------------

// Fused weights: W_top = Wc @ Wl_top, W_bot = Wl_bot, bias = bc @ Wl_top + bl.
// Also zeroes the edge counters (needed fresh every graph replay).
__global__ void k_prep(WPtrs P) {
    int flat = (blockIdx.y * gridDim.x + blockIdx.x) * blockDim.x + threadIdx.x;
    if (flat < NN) { g_count[flat] = 0; g_degsum[flat] = 0.f; }

    int lg = blockIdx.y;                // 0..5
    int l = lg / 3, g = lg % 3;
    int i = blockIdx.x;                 // row 0..127
    int j = threadIdx.x;                // col 0..127
    const float* Wc = P.Wc[g] + l * HH * HH;
    const float* Wl = P.Wl[g] + l * 2 * HH * HH;
    float c = 0.f;
    for (int k = 0; k < HH; k++) c += Wc[i * HH + k] * Wl[k * HH + j];
    float bot = Wl[(HH + i) * HH + j];
    if (g < 2) {
        g_Wzr[l * 256 * 256 + i * 256 + g * HH + j] = c;
        g_Wzr[l * 256 * 256 + (HH + i) * 256 + g * HH + j] = bot;
    } else {
        g_Wh[l * 256 * 128 + i * 128 + j] = c;
        g_Wh[l * 256 * 128 + (HH + i) * 128 + j] = bot;
    }
    if (i == 0) {
        const float* bc = P.bc[g] + l * HH;
        const float* bl = P.bl[g] + l * HH;
        float b = 0.f;
        for (int k = 0; k < HH; k++) b += bc[k] * Wl[k * HH + j];
        b += bl[j];
        if (g < 2) g_bzr[l * 256 + g * HH + j] = b;
        else       g_bh[l * 128 + j] = b;
    }
}

// Transpose x (N,F,T)->(T,N,F), zero states, and count edges per dst.
__global__ void k_init(const float* __restrict__ x,
                       const int* __restrict__ ei, const float* __restrict__ ew) {
    int idx = blockIdx.x * blockDim.x + threadIdx.x;   // over N*F
    if (idx >= NN * FF) return;
    const float4* xr = (const float4*)(x + (size_t)idx * TT);
    float v[16];
    float4 q;
    q = xr[0]; v[0]=q.x; v[1]=q.y; v[2]=q.z; v[3]=q.w;
    q = xr[1]; v[4]=q.x; v[5]=q.y; v[6]=q.z; v[7]=q.w;
    q = xr[2]; v[8]=q.x; v[9]=q.y; v[10]=q.z; v[11]=q.w;
    q = xr[3]; v[12]=q.x; v[13]=q.y; v[14]=q.z; v[15]=q.w;
#pragma unroll
    for (int t = 0; t < TT; t++)
        g_xT[t * (NN * FF) + idx] = v[t];
    g_h0[idx] = 0.f;
    g_h1[idx] = 0.f;
    if (idx < EE) {
        int d = ei[EE + idx];
        atomicAdd(&g_count[d], 1);
        atomicAdd(&g_degsum[d], ew[idx]);
    }
}

__global__ void k_scan() {
    __shared__ int sdata[1024];
    __shared__ int s_off;
    int tid = threadIdx.x;
    for (int i = tid; i < NN; i += 1024) {
        float dinv = rsqrtf(g_degsum[i] + 1.0f);
        g_dinv[i] = dinv;
        g_selfn[i] = dinv * dinv;
    }
    if (tid == 0) s_off = 0;
    __syncthreads();
    for (int base = 0; base < NN; base += 1024) {
        int v = (base + tid < NN) ? g_count[base + tid] : 0;
        sdata[tid] = v;
        __syncthreads();
        for (int d = 1; d < 1024; d <<= 1) {
            int t2 = (tid >= d) ? sdata[tid - d] : 0;
            __syncthreads();
            sdata[tid] += t2;
            __syncthreads();
        }
        int excl = sdata[tid] - v;
        if (base + tid < NN) {
            g_rowptr[base + tid] = s_off + excl;
            g_cursor[base + tid] = s_off + excl;
        }
        __syncthreads();
        int chunk_total = sdata[1023];
        if (tid == 0) s_off += chunk_total;
        __syncthreads();
    }
    if (tid == 0) g_rowptr[NN] = s_off;
}

__global__ void k_scatter(const int* __restrict__ ei, const float* __restrict__ ew) {
    int e = blockIdx.x * blockDim.x + threadIdx.x;
    if (e >= EE) return;
    int s = ei[e], d = ei[EE + e];
    int p = atomicAdd(&g_cursor[d], 1);
    g_cols[p] = s;
    g_vals[p] = ew[e] * g_dinv[s] * g_dinv[d];
}

// ---------------- main-loop kernels ----------------

// g_agg[row] = A_norm @ in (incl. self-loop term)
__global__ void k_spmm(const float* __restrict__ in) {
    int row = blockIdx.x * blockDim.y + threadIdx.y;
    if (row >= NN) return;
    int lane = threadIdx.x;
    const float4* in4 = (const float4*)in;
    float sn = g_selfn[row];
    float4 hv = in4[row * 32 + lane];
    float ax = sn * hv.x, ay = sn * hv.y, az = sn * hv.z, aw = sn * hv.w;
    float bx = 0.f, by = 0.f, bz = 0.f, bw = 0.f;
    int p = g_rowptr[row], pe = g_rowptr[row + 1];
    for (; p + 1 < pe; p += 2) {
        float v0 = g_vals[p],     v1 = g_vals[p + 1];
        int   c0 = g_cols[p],     c1 = g_cols[p + 1];
        float4 b0 = in4[c0 * 32 + lane];
        float4 b1 = in4[c1 * 32 + lane];
        ax += v0 * b0.x; ay += v0 * b0.y; az += v0 * b0.z; aw += v0 * b0.w;
        bx += v1 * b1.x; by += v1 * b1.y; bz += v1 * b1.z; bw += v1 * b1.w;
    }
    if (p < pe) {
        float v0 = g_vals[p]; int c0 = g_cols[p];
        float4 b0 = in4[c0 * 32 + lane];
        ax += v0 * b0.x; ay += v0 * b0.y; az += v0 * b0.z; aw += v0 * b0.w;
    }
    ((float4*)g_agg)[row * 32 + lane] =
        make_float4(ax + bx, ay + by, az + bz, aw + bw);
}

// ---------------- 3xTF32 tensor-core GEMM with fused epilogues ----------------
// Logical A = [A1 | A2] (M x 2*128) via two pointers; B is K x ldb row-major.
// Tile: BM=128 x BN (128 or 64), BK=16, 256 threads = 8 warps.
// BN=128: warps 4m x 2n, warp tile 32x64 (2 x 8 m16n8 tiles).
// BN=64 : warps 4m x 2n, warp tile 32x32 (2 x 4 tiles).
// 3 MMA passes per k8: hi*hi + hi*lo + lo*hi  (~21-bit effective mantissa).
// MODE 0: gate (N=256). blockIdx.y==0 -> g_zg = sigmoid; ==1 -> g_rh = sigmoid*hp.
// MODE 1: candidate.  h_new = z*hp + (1-z)*tanh; writes hstate (+ hseq if wseq).
// MODE 2: plain Cout = acc + bias.
template<int BN, int MODE>
__global__ void __launch_bounds__(256)
k_gemm_tc(const float* __restrict__ A1, const float* __restrict__ A2,
          const float* __restrict__ B, const float* __restrict__ bias,
          float* __restrict__ hstate, float* __restrict__ Cout,
          int M, int K, int ldb, int t, int wseq) {
    constexpr int SA = 20;        // A smem row stride (floats): conflict-free frag loads
    constexpr int SB = BN + 8;    // B smem row stride
    constexpr int WN = (BN == 128) ? 64 : 32;
    constexpr int NT = WN / 8;

    __shared__ float sAh[128 * SA];
    __shared__ float sAl[128 * SA];
    __shared__ float sBh[16 * SB];
    __shared__ float sBl[16 * SB];

    const int tid = threadIdx.x;
    const int lane = tid & 31;
    const int wid = tid >> 5;
    const int warp_m = wid & 3;       // 0..3
    const int warp_n = wid >> 2;      // 0..1
    const int row0 = blockIdx.x * 128;
    const int col0 = blockIdx.y * BN;

    float acc[2][NT][4];
#pragma unroll
    for (int i = 0; i < 2; i++)
#pragma unroll
        for (int j = 0; j < NT; j++)
#pragma unroll
            for (int q = 0; q < 4; q++) acc[i][j][q] = 0.f;

    for (int kt = 0; kt < K; kt += 16) {
        const float* Asrc = (kt < 128) ? A1 + kt : A2 + (kt - 128);
        // ---- load A tile (128 x 16) -> hi/lo smem ----
#pragma unroll
        for (int i = 0; i < 2; i++) {
            int lid = tid + i * 256;
            int m = lid >> 2, kq = (lid & 3) * 4;
            int grow = row0 + m;
            float4 a = (grow < M) ? *(const float4*)(Asrc + (size_t)grow * 128 + kq)
                                  : make_float4(0.f, 0.f, 0.f, 0.f);
            float4 h4, l4;
            uint32_t hb;
            hb = f2tf(a.x); h4.x = __uint_as_float(hb);
            l4.x = __uint_as_float(f2tf(a.x - h4.x));
            hb = f2tf(a.y); h4.y = __uint_as_float(hb);
            l4.y = __uint_as_float(f2tf(a.y - h4.y));
            hb = f2tf(a.z); h4.z = __uint_as_float(hb);
            l4.z = __uint_as_float(f2tf(a.z - h4.z));
            hb = f2tf(a.w); h4.w = __uint_as_float(hb);
            l4.w = __uint_as_float(f2tf(a.w - h4.w));
            *(float4*)&sAh[m * SA + kq] = h4;
            *(float4*)&sAl[m * SA + kq] = l4;
        }
        // ---- load B tile (16 x BN) -> hi/lo smem ----
        if (BN == 128) {
#pragma unroll
            for (int i = 0; i < 2; i++) {
                int lid = tid + i * 256;
                int k = lid >> 5, nq = (lid & 31) * 4;
                float4 b = *(const float4*)&B[(size_t)(kt + k) * ldb + col0 + nq];
                float4 h4, l4;
                h4.x = __uint_as_float(f2tf(b.x)); l4.x = __uint_as_float(f2tf(b.x - h4.x));
                h4.y = __uint_as_float(f2tf(b.y)); l4.y = __uint_as_float(f2tf(b.y - h4.y));
                h4.z = __uint_as_float(f2tf(b.z)); l4.z = __uint_as_float(f2tf(b.z - h4.z));
                h4.w = __uint_as_float(f2tf(b.w)); l4.w = __uint_as_float(f2tf(b.w - h4.w));
                *(float4*)&sBh[k * SB + nq] = h4;
                *(float4*)&sBl[k * SB + nq] = l4;
            }
        } else {
            int k = tid >> 4, nq = (tid & 15) * 4;
            float4 b = *(const float4*)&B[(size_t)(kt + k) * ldb + col0 + nq];
            float4 h4, l4;
            h4.x = __uint_as_float(f2tf(b.x)); l4.x = __uint_as_float(f2tf(b.x - h4.x));
            h4.y = __uint_as_float(f2tf(b.y)); l4.y = __uint_as_float(f2tf(b.y - h4.y));
            h4.z = __uint_as_float(f2tf(b.z)); l4.z = __uint_as_float(f2tf(b.z - h4.z));
            h4.w = __uint_as_float(f2tf(b.w)); l4.w = __uint_as_float(f2tf(b.w - h4.w));
            *(float4*)&sBh[k * SB + nq] = h4;
            *(float4*)&sBl[k * SB + nq] = l4;
        }
        __syncthreads();

#pragma unroll
        for (int k0 = 0; k0 < 16; k0 += 8) {
            // A fragments
            uint32_t ah[2][4], al[2][4];
#pragma unroll
            for (int mt = 0; mt < 2; mt++) {
                int r0 = (warp_m * 32 + mt * 16 + (lane >> 2)) * SA;
                int c0k = k0 + (lane & 3);
                ah[mt][0] = __float_as_uint(sAh[r0 + c0k]);
                ah[mt][1] = __float_as_uint(sAh[r0 + 8 * SA + c0k]);
                ah[mt][2] = __float_as_uint(sAh[r0 + c0k + 4]);
                ah[mt][3] = __float_as_uint(sAh[r0 + 8 * SA + c0k + 4]);
                al[mt][0] = __float_as_uint(sAl[r0 + c0k]);
                al[mt][1] = __float_as_uint(sAl[r0 + 8 * SA + c0k]);
                al[mt][2] = __float_as_uint(sAl[r0 + c0k + 4]);
                al[mt][3] = __float_as_uint(sAl[r0 + 8 * SA + c0k + 4]);
            }
            // B fragments
            uint32_t bh[NT][2], bl[NT][2];
#pragma unroll
            for (int nt = 0; nt < NT; nt++) {
                int ncol = warp_n * WN + nt * 8 + (lane >> 2);
                int kr = (k0 + (lane & 3)) * SB;
                bh[nt][0] = __float_as_uint(sBh[kr + ncol]);
                bh[nt][1] = __float_as_uint(sBh[kr + 4 * SB + ncol]);
                bl[nt][0] = __float_as_uint(sBl[kr + ncol]);
                bl[nt][1] = __float_as_uint(sBl[kr + 4 * SB + ncol]);
            }
            // 3 passes
#pragma unroll
            for (int mt = 0; mt < 2; mt++)
#pragma unroll
                for (int nt = 0; nt < NT; nt++) {
                    mma_tf32(acc[mt][nt], ah[mt], bh[nt]);
                    mma_tf32(acc[mt][nt], ah[mt], bl[nt]);
                    mma_tf32(acc[mt][nt], al[mt], bh[nt]);
                }
        }
        __syncthreads();
    }

    // ---- epilogue (fragment mapping: c0,c1 -> (r, c),(r, c+1); c2,c3 -> (r+8, ...)) ----
#pragma unroll
    for (int mt = 0; mt < 2; mt++) {
        int rbase = row0 + warp_m * 32 + mt * 16 + (lane >> 2);
#pragma unroll
        for (int nt = 0; nt < NT; nt++) {
            int gcol = col0 + warp_n * WN + nt * 8 + (lane & 3) * 2;   // within N
            float b0 = bias[gcol], b1 = bias[gcol + 1];
#pragma unroll
            for (int half = 0; half < 2; half++) {
                int row = rbase + half * 8;
                if (row >= M) continue;
                float v0 = acc[mt][nt][half * 2 + 0] + b0;
                float v1 = acc[mt][nt][half * 2 + 1] + b1;
                if (MODE == 0) {
                    v0 = 1.f / (1.f + expf(-v0));
                    v1 = 1.f / (1.f + expf(-v1));
                    if (col0 < 128) {
                        size_t base = (size_t)row * 128 + gcol;
                        *(float2*)&g_zg[base] = make_float2(v0, v1);
                    } else {
                        size_t base = (size_t)row * 128 + (gcol - 128);
                        float2 hv = *(const float2*)&hstate[base];
                        *(float2*)&g_rh[base] = make_float2(v0 * hv.x, v1 * hv.y);
                    }
                } else if (MODE == 1) {
                    size_t base = (size_t)row * 128 + gcol;
                    float2 zv = *(const float2*)&g_zg[base];
                    float2 hv = *(const float2*)&hstate[base];
                    float hn0 = zv.x * hv.x + (1.f - zv.x) * tanhf(v0);
                    float hn1 = zv.y * hv.y + (1.f - zv.y) * tanhf(v1);
                    *(float2*)&hstate[base] = make_float2(hn0, hn1);
                    if (wseq) {
                        size_t sb = (size_t)row * (TT * HH) + t * HH + gcol;
                        *(float2*)&g_hseq[sb] = make_float2(hn0, hn1);
                    }
                } else {
                    size_t base = (size_t)row * 128 + gcol;
                    *(float2*)&Cout[base] = make_float2(v0, v1);
                }
            }
        }
    }
}

// Temporal attention: warp per node (att_b cancels inside softmax).
__global__ void __launch_bounds__(128)
k_attn(const float* __restrict__ attW) {
    int n = blockIdx.x * blockDim.y + threadIdx.y;
    if (n >= NN) return;
    int lane = threadIdx.x;
    float4 aw = ((const float4*)attW)[lane];
    const float4* h4 = (const float4*)g_hseq + n * (TT * HH / 4) + lane;
    float4 hv[16];
    float s[16];
#pragma unroll
    for (int t = 0; t < TT; t++) {
        hv[t] = h4[t * 32];
        float d = hv[t].x * aw.x + hv[t].y * aw.y + hv[t].z * aw.z + hv[t].w * aw.w;
#pragma unroll
        for (int o = 16; o > 0; o >>= 1) d += __shfl_xor_sync(0xffffffffu, d, o);
        s[t] = d;
    }
    float m = s[0];
#pragma unroll
    for (int t = 1; t < TT; t++) m = fmaxf(m, s[t]);
    float sum = 0.f;
#pragma unroll
    for (int t = 0; t < TT; t++) { s[t] = expf(s[t] - m); sum += s[t]; }
    float inv = 1.f / sum;
    float4 c = make_float4(0.f, 0.f, 0.f, 0.f);
#pragma unroll
    for (int t = 0; t < TT; t++) {
        float w = s[t] * inv;
        c.x += w * hv[t].x; c.y += w * hv[t].y; c.z += w * hv[t].z; c.w += w * hv[t].w;
    }
    ((float4*)g_ctx)[n * 32 + lane] = c;
}

// ---------------- launch ----------------

extern "C" void kernel_launch(void* const* d_in, const int* in_sizes, int n_in,
                              void* d_out, int out_size) {
    const float* x   = (const float*)d_in[0];
    const int*   ei  = (const int*)d_in[1];
    const float* ew  = (const float*)d_in[2];
    WPtrs P;
    P.Wc[0] = (const float*)d_in[3];  P.bc[0] = (const float*)d_in[4];
    P.Wl[0] = (const float*)d_in[5];  P.bl[0] = (const float*)d_in[6];
    P.Wc[1] = (const float*)d_in[7];  P.bc[1] = (const float*)d_in[8];
    P.Wl[1] = (const float*)d_in[9];  P.bl[1] = (const float*)d_in[10];
    P.Wc[2] = (const float*)d_in[11]; P.bc[2] = (const float*)d_in[12];
    P.Wl[2] = (const float*)d_in[13]; P.bl[2] = (const float*)d_in[14];
    const float* attW = (const float*)d_in[15];
    const float* outW = (const float*)d_in[17];
    const float* outb = (const float*)d_in[18];
    float* out = (float*)d_out;

    float *p_xT, *p_h0, *p_h1, *p_agg, *p_rh, *p_ctx, *p_Wzr, *p_Wh, *p_bzr, *p_bh;
    cudaGetSymbolAddress((void**)&p_xT,  g_xT);
    cudaGetSymbolAddress((void**)&p_h0,  g_h0);
    cudaGetSymbolAddress((void**)&p_h1,  g_h1);
    cudaGetSymbolAddress((void**)&p_agg, g_agg);
    cudaGetSymbolAddress((void**)&p_rh,  g_rh);
    cudaGetSymbolAddress((void**)&p_ctx, g_ctx);
    cudaGetSymbolAddress((void**)&p_Wzr, g_Wzr);
    cudaGetSymbolAddress((void**)&p_Wh,  g_Wh);
    cudaGetSymbolAddress((void**)&p_bzr, g_bzr);
    cudaGetSymbolAddress((void**)&p_bh,  g_bh);

    const int GX = (NN + 127) / 128;                // 79

    k_prep<<<dim3(HH, 6), HH>>>(P);
    k_init<<<(NN * FF + 255) / 256, 256>>>(x, ei, ew);
    k_scan<<<1, 1024>>>();
    k_scatter<<<(EE + 255) / 256, 256>>>(ei, ew);

    for (int t = 0; t < TT; t++) {
        // ---- layer 0 (input = x_t) ----
        k_spmm<<<(NN + 7) / 8, dim3(32, 8)>>>(p_xT + (size_t)t * NN * FF);
        k_gemm_tc<128, 0><<<dim3(GX, 2), 256>>>(p_agg, p_h0, p_Wzr, p_bzr,
                                                p_h0, nullptr, NN, 256, 256, 0, 0);
        k_gemm_tc<64, 1><<<dim3(GX, 2), 256>>>(p_agg, p_rh, p_Wh, p_bh,
                                               p_h0, nullptr, NN, 256, 128, t, 0);
        // ---- layer 1 (input = new h0) ----
        k_spmm<<<(NN + 7) / 8, dim3(32, 8)>>>(p_h0);
        k_gemm_tc<128, 0><<<dim3(GX, 2), 256>>>(p_agg, p_h1, p_Wzr + 256 * 256, p_bzr + 256,
                                                p_h1, nullptr, NN, 256, 256, 0, 0);
        k_gemm_tc<64, 1><<<dim3(GX, 2), 256>>>(p_agg, p_rh, p_Wh + 256 * 128, p_bh + 128,
                                               p_h1, nullptr, NN, 256, 128, t, 1);
    }

    k_attn<<<(NN + 3) / 4, dim3(32, 4)>>>(attW);
    k_gemm_tc<64, 2><<<dim3(GX, 2), 256>>>(p_ctx, p_ctx, outW, outb,
                                           nullptr, out, NN, 128, 128, 0, 0);
}